// round 16
// baseline (speedup 1.0000x reference)
#include <cuda_runtime.h>
#include <cuda_fp16.h>
#include <cstdint>

// ============================================================================
// SelfAttention: out = softmax( (xWq^T+bq)(xWk^T+bk)^T ) (xWv^T+bv)
// B=4, S=2048, H=1024 (fp32 in/out)
// q_i.k_j = x_i (Wq^T Wk) x_j^T + rowconst + w_j ; rowconst cancels.
// M = Wq^T Wk + v = x.Wv^T+bv (merged); y = x.M (split3, also emits int8 yq).
// Scores: APPROX INT8 GEMM gate; epilogue FOLDS w into stored fp16 logits and
// emits per-(row,tile) maxima (g_tmax) so the fused kernel derives the row max
// from 16 floats.  Candidates (margin 22.5) are rescored exactly in fp32,
// then exp/normalize/gather-v in one fused kernel.
// ============================================================================

#define BATCH 4
#define SEQ   2048
#define HID   1024
#define MTOT  (BATCH*SEQ)          // 8192

#define QINV   (127.0f/8.0f)
#define SSCALE ((8.0f/127.0f)*(8.0f/127.0f))

// ---- scratch (device globals; allocation-free per harness rules) ----
__device__ __half g_xh[(size_t)MTOT * HID];
__device__ __half g_xl[(size_t)MTOT * HID];
__device__ int8_t g_xq[(size_t)MTOT * HID];
__device__ __half g_wqt_h[(size_t)HID * HID];
__device__ __half g_wqt_l[(size_t)HID * HID];
__device__ __half g_wk_h[(size_t)HID * HID];
__device__ __half g_wk_l[(size_t)HID * HID];
__device__ __half g_wv_h[(size_t)HID * HID];
__device__ __half g_mh[(size_t)HID * HID];
__device__ __half g_ml[(size_t)HID * HID];
__device__ __half g_yh[(size_t)MTOT * HID];
__device__ __half g_yl[(size_t)MTOT * HID];
__device__ int8_t g_yq[(size_t)MTOT * HID];
__device__ __half g_vh[(size_t)MTOT * HID];
__device__ __half g_s [(size_t)BATCH * SEQ * SEQ];   // approx logits (s+w, fp16)
__device__ float  g_tmax[(size_t)MTOT * 16];         // per-(row,tile) max
__device__ float  g_w [MTOT];
__device__ float  g_t2[HID];
__device__ float  g_t2p[32][HID];
__device__ float  g_zero[HID];

// ----------------------------------------------------------------------------
// helpers
// ----------------------------------------------------------------------------
__device__ __forceinline__ uint32_t smem_u32(const void* p) {
    uint32_t a;
    asm("{ .reg .u64 t; cvta.to.shared.u64 t, %1; cvt.u32.u64 %0, t; }"
        : "=r"(a) : "l"(p));
    return a;
}

__device__ __forceinline__ void cpa16(uint32_t dst, const void* src) {
    asm volatile("cp.async.cg.shared.global [%0], [%1], 16;"
                 :: "r"(dst), "l"(src));
}

__device__ __forceinline__ void ldsm4(uint32_t& r0, uint32_t& r1,
                                      uint32_t& r2, uint32_t& r3, uint32_t a) {
    asm volatile("ldmatrix.sync.aligned.m8n8.x4.shared.b16 {%0,%1,%2,%3}, [%4];"
                 : "=r"(r0), "=r"(r1), "=r"(r2), "=r"(r3) : "r"(a));
}
__device__ __forceinline__ void ldsm4t(uint32_t& r0, uint32_t& r1,
                                       uint32_t& r2, uint32_t& r3, uint32_t a) {
    asm volatile("ldmatrix.sync.aligned.m8n8.x4.trans.shared.b16 {%0,%1,%2,%3}, [%4];"
                 : "=r"(r0), "=r"(r1), "=r"(r2), "=r"(r3) : "r"(a));
}

__device__ __forceinline__ void mma16816(float c[4], const uint32_t a[4],
                                         uint32_t b0, uint32_t b1) {
    asm volatile(
        "mma.sync.aligned.m16n8k16.row.col.f32.f16.f16.f32 "
        "{%0,%1,%2,%3}, {%4,%5,%6,%7}, {%8,%9}, {%0,%1,%2,%3};\n"
        : "+f"(c[0]), "+f"(c[1]), "+f"(c[2]), "+f"(c[3])
        : "r"(a[0]), "r"(a[1]), "r"(a[2]), "r"(a[3]), "r"(b0), "r"(b1));
}

__device__ __forceinline__ void mma_s8(int c[4], const uint32_t a[4],
                                       uint32_t b0, uint32_t b1) {
    asm volatile(
        "mma.sync.aligned.m16n8k32.row.col.s32.s8.s8.s32 "
        "{%0,%1,%2,%3}, {%4,%5,%6,%7}, {%8,%9}, {%0,%1,%2,%3};\n"
        : "+r"(c[0]), "+r"(c[1]), "+r"(c[2]), "+r"(c[3])
        : "r"(a[0]), "r"(a[1]), "r"(a[2]), "r"(a[3]), "r"(b0), "r"(b1));
}

__device__ __forceinline__ int8_t quant8(float x) {
    const float q = fminf(fmaxf(x * QINV, -127.f), 127.f);
    return (int8_t)__float2int_rn(q);
}

// ============================================================================
// FP16 GEMM core: 128x128 tile, BK=64, 3-stage cp.async.
//   EPI: 0 fp32 | 1 bias + split half | 2 bias + half | 4 split half + int8
// ============================================================================
template<int KVAL, int NSPLIT, bool BNN, int EPI>
__device__ __forceinline__ void gemm_main(
    const __half* __restrict__ Ah, const __half* __restrict__ Al,
    const __half* __restrict__ Bh, const __half* __restrict__ Bl,
    int lda, int ldb,
    float* __restrict__ Cf, __half* __restrict__ Ch, __half* __restrict__ Cl,
    const float* __restrict__ bias, int ldc,
    int tm0, int tn0)
{
    constexpr int NC = KVAL / 64;
    constexpr int T  = NSPLIT * NC;
    constexpr int STAGES = 3;
    constexpr uint32_t STAGE = 32768u;

    extern __shared__ __align__(16) char smem[];
    const uint32_t sbase = smem_u32(smem);

    const int tid  = threadIdx.x;
    const int lane = tid & 31;
    const int warp = tid >> 5;
    const int wm = warp & 3;
    const int wn = warp >> 2;

    uint32_t dA[4], gA[4], dB[4], gB[4];
    #pragma unroll
    for (int i = 0; i < 4; ++i) {
        const int slot = tid + i * 256;
        { const int r = slot >> 3, c = slot & 7;
          dA[i] = (uint32_t)(r * 128 + ((c ^ (r & 7)) << 4));
          gA[i] = (uint32_t)((tm0 + r) * lda + c * 8); }
        if (!BNN) {
            const int r = slot >> 3, c = slot & 7;
            dB[i] = (uint32_t)(r * 128 + ((c ^ (r & 7)) << 4));
            gB[i] = (uint32_t)((tn0 + r) * ldb + c * 8);
        } else {
            const int r = slot >> 4, c = slot & 15;
            dB[i] = (uint32_t)(r * 256 + ((c ^ (r & 7)) << 4));
            gB[i] = (uint32_t)(r * ldb + tn0 + c * 8);
        }
    }

    const __half* const Alist[3] = {Ah, Ah, Al};
    const __half* const Blist[3] = {Bh, Bl, Bh};

    const uint32_t kcoA = (lane >> 4) & 1;
    uint32_t aoff[2], asw[2];
    {
        const int roff = (lane & 7) + (((lane >> 3) & 1) << 3);
        #pragma unroll
        for (int mi = 0; mi < 2; ++mi) {
            const int r = wm * 32 + mi * 16 + roff;
            aoff[mi] = (uint32_t)(r * 128);
            asw[mi]  = (uint32_t)(r & 7);
        }
    }
    const uint32_t kcoB = (lane >> 3) & 1;
    uint32_t boff[4], bsw[4];
    uint32_t bco[4], bkoff = 0;
    if (!BNN) {
        const int noff = (lane & 7) + (((lane >> 4) & 1) << 3);
        #pragma unroll
        for (int p = 0; p < 4; ++p) {
            const int r = wn * 64 + p * 16 + noff;
            boff[p] = (uint32_t)(r * 128);
            bsw[p]  = (uint32_t)(r & 7);
        }
    } else {
        const int koff = (lane & 7) + (((lane >> 3) & 1) << 3);
        bkoff = (uint32_t)(koff * 256);
        const int ncsel = (lane >> 4) & 1;
        #pragma unroll
        for (int p = 0; p < 4; ++p) {
            const int ncb = wn * 8 + p * 2 + ncsel;
            bco[p] = (uint32_t)((ncb ^ (lane & 7)) << 4);
        }
    }

    float acc[2][8][4];
    #pragma unroll
    for (int mi = 0; mi < 2; ++mi)
        #pragma unroll
        for (int ni = 0; ni < 8; ++ni)
            #pragma unroll
            for (int j = 0; j < 4; ++j) acc[mi][ni][j] = 0.f;

    auto issue = [&](int t) {
        int comp, kc;
        if (NSPLIT == 1) { comp = 0; kc = t; }
        else             { comp = t / NC; kc = t - comp * NC; }
        const int k0 = kc * 64;
        const __half* Ap = Alist[comp];
        const __half* Bp = Blist[comp];
        const uint32_t s = sbase + (uint32_t)(t % STAGES) * STAGE;
        #pragma unroll
        for (int i = 0; i < 4; ++i) {
            cpa16(s + dA[i], Ap + gA[i] + k0);
            if (!BNN) cpa16(s + 16384u + dB[i], Bp + gB[i] + k0);
            else      cpa16(s + 16384u + dB[i], Bp + gB[i] + (size_t)k0 * ldb);
        }
    };

    #pragma unroll
    for (int s = 0; s < STAGES - 1; ++s) {
        if (s < T) issue(s);
        asm volatile("cp.async.commit_group;");
    }

    for (int t = 0; t < T; ++t) {
        asm volatile("cp.async.wait_group 1;");
        __syncthreads();
        if (t + STAGES - 1 < T) issue(t + STAGES - 1);
        asm volatile("cp.async.commit_group;");

        const uint32_t sA = sbase + (uint32_t)(t % STAGES) * STAGE;
        const uint32_t sB = sA + 16384u;
        #pragma unroll
        for (int kk = 0; kk < 4; ++kk) {
            uint32_t a[2][4];
            #pragma unroll
            for (int mi = 0; mi < 2; ++mi)
                ldsm4(a[mi][0], a[mi][1], a[mi][2], a[mi][3],
                      sA + aoff[mi] + ((((uint32_t)(2 * kk) + kcoA) ^ asw[mi]) << 4));
            uint32_t b[4][4];
            #pragma unroll
            for (int p = 0; p < 4; ++p) {
                if (!BNN)
                    ldsm4(b[p][0], b[p][1], b[p][2], b[p][3],
                          sB + boff[p] + ((((uint32_t)(2 * kk) + kcoB) ^ bsw[p]) << 4));
                else
                    ldsm4t(b[p][0], b[p][1], b[p][2], b[p][3],
                           sB + (uint32_t)kk * 4096u + bkoff + bco[p]);
            }
            #pragma unroll
            for (int mi = 0; mi < 2; ++mi)
                #pragma unroll
                for (int p = 0; p < 4; ++p) {
                    mma16816(acc[mi][2 * p],     a[mi], b[p][0], b[p][1]);
                    mma16816(acc[mi][2 * p + 1], a[mi], b[p][2], b[p][3]);
                }
        }
    }

    const int gid = lane >> 2, qid = lane & 3;
    #pragma unroll
    for (int mi = 0; mi < 2; ++mi) {
        #pragma unroll
        for (int ni = 0; ni < 8; ++ni) {
            const int r = tm0 + wm * 32 + mi * 16 + gid;
            const int c = tn0 + wn * 64 + ni * 8 + qid * 2;
            float v0 = acc[mi][ni][0], v1 = acc[mi][ni][1];
            float v2 = acc[mi][ni][2], v3 = acc[mi][ni][3];
            if (EPI == 1 || EPI == 2) {
                const float2 bb = *reinterpret_cast<const float2*>(bias + c);
                v0 += bb.x; v1 += bb.y; v2 += bb.x; v3 += bb.y;
            }
            if (EPI == 0) {
                *reinterpret_cast<float2*>(Cf + (size_t)r * ldc + c) =
                    make_float2(v0, v1);
                *reinterpret_cast<float2*>(Cf + (size_t)(r + 8) * ldc + c) =
                    make_float2(v2, v3);
            } else if (EPI == 2) {
                *reinterpret_cast<__half2*>(Ch + (size_t)r * ldc + c) =
                    __halves2half2(__float2half_rn(v0), __float2half_rn(v1));
                *reinterpret_cast<__half2*>(Ch + (size_t)(r + 8) * ldc + c) =
                    __halves2half2(__float2half_rn(v2), __float2half_rn(v3));
            } else {
                const __half h0 = __float2half_rn(v0), h1 = __float2half_rn(v1);
                const __half h2 = __float2half_rn(v2), h3 = __float2half_rn(v3);
                *reinterpret_cast<__half2*>(Ch + (size_t)r * ldc + c) =
                    __halves2half2(h0, h1);
                *reinterpret_cast<__half2*>(Ch + (size_t)(r + 8) * ldc + c) =
                    __halves2half2(h2, h3);
                *reinterpret_cast<__half2*>(Cl + (size_t)r * ldc + c) =
                    __halves2half2(__float2half_rn(v0 - __half2float(h0)),
                                   __float2half_rn(v1 - __half2float(h1)));
                *reinterpret_cast<__half2*>(Cl + (size_t)(r + 8) * ldc + c) =
                    __halves2half2(__float2half_rn(v2 - __half2float(h2)),
                                   __float2half_rn(v3 - __half2float(h3)));
                if (EPI == 4) {
                    char2 q01; q01.x = quant8(v0); q01.y = quant8(v1);
                    char2 q23; q23.x = quant8(v2); q23.y = quant8(v3);
                    *reinterpret_cast<char2*>(g_yq + (size_t)r * ldc + c) = q01;
                    *reinterpret_cast<char2*>(g_yq + (size_t)(r + 8) * ldc + c) = q23;
                }
            }
        }
    }
}

// ============================================================================
// INT8 GEMM core (TN): s8 in, s32 accum.  Epilogue folds w into the stored
// fp16 approx logits and emits per-(row, tile) maxima to tmaxp (stride 16).
// ============================================================================
template<int KVAL>
__device__ __forceinline__ void gemm_s8(
    const int8_t* __restrict__ A, const int8_t* __restrict__ B,
    int lda, int ldb, __half* __restrict__ C, int ldc,
    int tm0, int tn0,
    const float* __restrict__ wrow, float* __restrict__ tmaxp)
{
    constexpr int T = KVAL / 128;
    constexpr int STAGES = 3;
    constexpr uint32_t STAGE = 32768u;

    extern __shared__ __align__(16) char smem[];
    const uint32_t sbase = smem_u32(smem);
    __shared__ float sm_max[2][128];

    const int tid  = threadIdx.x;
    const int lane = tid & 31;
    const int warp = tid >> 5;
    const int wm = warp & 3;
    const int wn = warp >> 2;

    uint32_t dA[4], gA[4], gB[4];
    #pragma unroll
    for (int i = 0; i < 4; ++i) {
        const int slot = tid + i * 256;
        const int r = slot >> 3, c = slot & 7;
        dA[i] = (uint32_t)(r * 128 + ((c ^ (r & 7)) << 4));
        gA[i] = (uint32_t)((tm0 + r) * lda + c * 16);
        gB[i] = (uint32_t)((tn0 + r) * ldb + c * 16);
    }

    const uint32_t kcoA = (lane >> 4) & 1;
    uint32_t aoff[2], asw[2];
    {
        const int roff = (lane & 7) + (((lane >> 3) & 1) << 3);
        #pragma unroll
        for (int mi = 0; mi < 2; ++mi) {
            const int r = wm * 32 + mi * 16 + roff;
            aoff[mi] = (uint32_t)(r * 128);
            asw[mi]  = (uint32_t)(r & 7);
        }
    }
    const uint32_t kcoB = (lane >> 3) & 1;
    uint32_t boff[4], bsw[4];
    {
        const int noff = (lane & 7) + (((lane >> 4) & 1) << 3);
        #pragma unroll
        for (int p = 0; p < 4; ++p) {
            const int r = wn * 64 + p * 16 + noff;
            boff[p] = (uint32_t)(r * 128);
            bsw[p]  = (uint32_t)(r & 7);
        }
    }

    int acc[2][8][4];
    #pragma unroll
    for (int mi = 0; mi < 2; ++mi)
        #pragma unroll
        for (int ni = 0; ni < 8; ++ni)
            #pragma unroll
            for (int j = 0; j < 4; ++j) acc[mi][ni][j] = 0;

    auto issue = [&](int t) {
        const int k0 = t * 128;
        const uint32_t s = sbase + (uint32_t)(t % STAGES) * STAGE;
        #pragma unroll
        for (int i = 0; i < 4; ++i) {
            cpa16(s + dA[i], A + gA[i] + k0);
            cpa16(s + 16384u + dA[i], B + gB[i] + k0);
        }
    };

    #pragma unroll
    for (int s = 0; s < STAGES - 1; ++s) {
        if (s < T) issue(s);
        asm volatile("cp.async.commit_group;");
    }

    for (int t = 0; t < T; ++t) {
        asm volatile("cp.async.wait_group 1;");
        __syncthreads();
        if (t + STAGES - 1 < T) issue(t + STAGES - 1);
        asm volatile("cp.async.commit_group;");

        const uint32_t sA = sbase + (uint32_t)(t % STAGES) * STAGE;
        const uint32_t sB = sA + 16384u;
        #pragma unroll
        for (int kk = 0; kk < 4; ++kk) {
            uint32_t a[2][4];
            #pragma unroll
            for (int mi = 0; mi < 2; ++mi)
                ldsm4(a[mi][0], a[mi][1], a[mi][2], a[mi][3],
                      sA + aoff[mi] + ((((uint32_t)(2 * kk) + kcoA) ^ asw[mi]) << 4));
            uint32_t b[4][4];
            #pragma unroll
            for (int p = 0; p < 4; ++p)
                ldsm4(b[p][0], b[p][1], b[p][2], b[p][3],
                      sB + boff[p] + ((((uint32_t)(2 * kk) + kcoB) ^ bsw[p]) << 4));
            #pragma unroll
            for (int mi = 0; mi < 2; ++mi)
                #pragma unroll
                for (int p = 0; p < 4; ++p) {
                    mma_s8(acc[mi][2 * p],     a[mi], b[p][0], b[p][1]);
                    mma_s8(acc[mi][2 * p + 1], a[mi], b[p][2], b[p][3]);
                }
        }
    }

    // ---- epilogue: descale, add w, store fp16, per-row tile max ----
    const int gid = lane >> 2, qid = lane & 3;
    float rmax[2][2];
    rmax[0][0] = rmax[0][1] = rmax[1][0] = rmax[1][1] = -3.4e38f;
    #pragma unroll
    for (int mi = 0; mi < 2; ++mi) {
        #pragma unroll
        for (int ni = 0; ni < 8; ++ni) {
            const int r = tm0 + wm * 32 + mi * 16 + gid;
            const int c = tn0 + wn * 64 + ni * 8 + qid * 2;
            const float2 wv = *reinterpret_cast<const float2*>(wrow + c);
            const float v0 = (float)acc[mi][ni][0] * SSCALE + wv.x;
            const float v1 = (float)acc[mi][ni][1] * SSCALE + wv.y;
            const float v2 = (float)acc[mi][ni][2] * SSCALE + wv.x;
            const float v3 = (float)acc[mi][ni][3] * SSCALE + wv.y;
            *reinterpret_cast<__half2*>(C + (size_t)r * ldc + c) =
                __halves2half2(__float2half_rn(v0), __float2half_rn(v1));
            *reinterpret_cast<__half2*>(C + (size_t)(r + 8) * ldc + c) =
                __halves2half2(__float2half_rn(v2), __float2half_rn(v3));
            rmax[mi][0] = fmaxf(rmax[mi][0], fmaxf(v0, v1));
            rmax[mi][1] = fmaxf(rmax[mi][1], fmaxf(v2, v3));
        }
    }
    #pragma unroll
    for (int off = 1; off < 4; off <<= 1) {
        #pragma unroll
        for (int mi = 0; mi < 2; ++mi) {
            rmax[mi][0] = fmaxf(rmax[mi][0],
                                __shfl_xor_sync(0xffffffffu, rmax[mi][0], off));
            rmax[mi][1] = fmaxf(rmax[mi][1],
                                __shfl_xor_sync(0xffffffffu, rmax[mi][1], off));
        }
    }
    if (qid == 0) {
        #pragma unroll
        for (int mi = 0; mi < 2; ++mi) {
            sm_max[wn][wm * 32 + mi * 16 + gid]     = rmax[mi][0];
            sm_max[wn][wm * 32 + mi * 16 + gid + 8] = rmax[mi][1];
        }
    }
    __syncthreads();
    if (tid < 128)
        tmaxp[(size_t)tid * 16] = fmaxf(sm_max[0][tid], sm_max[1][tid]);
}

// ----------------------------------------------------------------------------
// prep kernels
// ----------------------------------------------------------------------------
__device__ __forceinline__ void split4(const float4 v, __half2* dh, __half2* dl) {
    const __half h0 = __float2half_rn(v.x), h1 = __float2half_rn(v.y);
    const __half h2 = __float2half_rn(v.z), h3 = __float2half_rn(v.w);
    dh[0] = __halves2half2(h0, h1);
    dh[1] = __halves2half2(h2, h3);
    dl[0] = __halves2half2(__float2half_rn(v.x - __half2float(h0)),
                           __float2half_rn(v.y - __half2float(h1)));
    dl[1] = __halves2half2(__float2half_rn(v.z - __half2float(h2)),
                           __float2half_rn(v.w - __half2float(h3)));
}

__global__ __launch_bounds__(256)
void split_x_kernel(const float* __restrict__ src)
{
    const int i = blockIdx.x * blockDim.x + threadIdx.x;
    const float4 v = reinterpret_cast<const float4*>(src)[i];
    split4(v, reinterpret_cast<__half2*>(g_xh) + 2 * i,
              reinterpret_cast<__half2*>(g_xl) + 2 * i);
    char4 q;
    q.x = quant8(v.x); q.y = quant8(v.y);
    q.z = quant8(v.z); q.w = quant8(v.w);
    reinterpret_cast<char4*>(g_xq)[i] = q;
}

__global__ __launch_bounds__(256)
void wkv_prep_kernel(const float* __restrict__ Wk, const float* __restrict__ Wv)
{
    const int i = blockIdx.x * blockDim.x + threadIdx.x;
    if (blockIdx.z == 0) {
        const float4 v = reinterpret_cast<const float4*>(Wk)[i];
        split4(v, reinterpret_cast<__half2*>(g_wk_h) + 2 * i,
                  reinterpret_cast<__half2*>(g_wk_l) + 2 * i);
    } else {
        const float4 v = reinterpret_cast<const float4*>(Wv)[i];
        reinterpret_cast<__half2*>(g_wv_h)[2 * i] =
            __halves2half2(__float2half_rn(v.x), __float2half_rn(v.y));
        reinterpret_cast<__half2*>(g_wv_h)[2 * i + 1] =
            __halves2half2(__float2half_rn(v.z), __float2half_rn(v.w));
    }
}

__global__ __launch_bounds__(256)
void wq_transpose_kernel(const float* __restrict__ Wq)
{
    __shared__ float s[32][33];
    const int a0 = blockIdx.x * 32, d0 = blockIdx.y * 32;
    const int tx = threadIdx.x & 31, ty = threadIdx.x >> 5;
    #pragma unroll
    for (int i = 0; i < 4; ++i) {
        const int d = d0 + ty + 8 * i;
        s[ty + 8 * i][tx] = Wq[(size_t)d * HID + a0 + tx];
    }
    __syncthreads();
    #pragma unroll
    for (int i = 0; i < 4; ++i) {
        const int a = a0 + ty + 8 * i;
        const float v = s[tx][ty + 8 * i];
        const __half h = __float2half_rn(v);
        g_wqt_h[(size_t)a * HID + d0 + tx] = h;
        g_wqt_l[(size_t)a * HID + d0 + tx] =
            __float2half_rn(v - __half2float(h));
    }
}

__global__ __launch_bounds__(256)
void t2_part_kernel(const float* __restrict__ Wk, const float* __restrict__ bq)
{
    const int a  = blockIdx.x * 256 + threadIdx.x;
    const int d0 = blockIdx.y * 32;
    float acc = 0.f;
    #pragma unroll
    for (int i = 0; i < 32; ++i)
        acc += Wk[(size_t)(d0 + i) * HID + a] * bq[d0 + i];
    g_t2p[blockIdx.y][a] = acc;
}

__global__ __launch_bounds__(256)
void t2_reduce_kernel()
{
    const int a = blockIdx.x * 256 + threadIdx.x;
    float acc = 0.f;
    #pragma unroll
    for (int z = 0; z < 32; ++z)
        acc += g_t2p[z][a];
    g_t2[a] = acc;
}

__global__ __launch_bounds__(128)
void w_kernel(const float* __restrict__ x)
{
    const int warp = threadIdx.x >> 5, lane = threadIdx.x & 31;
    const int row = blockIdx.x * 4 + warp;
    const float* xr = x + (size_t)row * HID;
    float s = 0.f;
    for (int a = lane; a < HID; a += 32) s += xr[a] * g_t2[a];
    #pragma unroll
    for (int off = 16; off; off >>= 1)
        s += __shfl_xor_sync(0xffffffffu, s, off);
    if (lane == 0) g_w[row] = s;
}

// ----------------------------------------------------------------------------
// GEMM kernels
// ----------------------------------------------------------------------------
__global__ __launch_bounds__(256, 2)
void mv_kernel(const float* __restrict__ bv)
{
    if (blockIdx.y < 8)
        gemm_main<1024, 3, true, 1>(g_wqt_h, g_wqt_l, g_wk_h, g_wk_l, HID, HID,
                                    nullptr, g_mh, g_ml, g_zero, HID,
                                    blockIdx.y * 128, blockIdx.x * 128);
    else
        gemm_main<1024, 1, false, 2>(g_xh, nullptr, g_wv_h, nullptr, HID, HID,
                                     nullptr, g_vh, nullptr, bv, HID,
                                     (blockIdx.y - 8) * 128, blockIdx.x * 128);
}

__global__ __launch_bounds__(256, 2)
void y_kernel()
{
    gemm_main<1024, 3, true, 4>(g_xh, g_xl, g_mh, g_ml, HID, HID,
                                nullptr, g_yh, g_yl, g_zero, HID,
                                blockIdx.y * 128, blockIdx.x * 128);
}

__global__ __launch_bounds__(256, 2)
void scores_kernel()
{
    const int z = blockIdx.z;
    const size_t bo = (size_t)z * SEQ * HID;
    gemm_s8<1024>(g_yq + bo, g_xq + bo, HID, HID,
                  g_s + (size_t)z * SEQ * SEQ, SEQ,
                  blockIdx.y * 128, blockIdx.x * 128,
                  g_w + (size_t)z * SEQ,
                  g_tmax + ((size_t)(z * SEQ + blockIdx.y * 128)) * 16
                         + blockIdx.x);
}

// ----------------------------------------------------------------------------
// Fused gate + exact rescore + softmax + P.v gather.
// Approx logits (s+w, fp16) pre-stored; row max derived from 16 tile maxima.
// Margin 22.5 covers int8 + fp16-store error with >=4 ulp slack.
// ----------------------------------------------------------------------------
__global__ __launch_bounds__(256)
void softmax_rescore_pv_kernel(float* __restrict__ out)
{
    const int row = blockIdx.x;
    const int batch = row >> 11;
    const int wbase = batch << 11;
    const __half* srow = g_s + (size_t)row * SEQ;
    const int t = threadIdx.x, lane = t & 31, wid = t >> 5;

    __shared__ float red[8];
    __shared__ int   s_wtot[8];
    __shared__ int   s_wbase[8];
    __shared__ int   s_ncand;
    __shared__ int   s_idx[SEQ];
    __shared__ float s_logit[SEQ];
    __shared__ float s_y[HID];

    // ---- y row -> smem fp32 (yh + yl) ----
    {
        const __half2* yh2 = reinterpret_cast<const __half2*>(g_yh + (size_t)row * HID);
        const __half2* yl2 = reinterpret_cast<const __half2*>(g_yl + (size_t)row * HID);
        #pragma unroll
        for (int i = 0; i < 2; ++i) {
            const int k = t + i * 256;
            const float2 h = __half22float2(yh2[k]);
            const float2 l = __half22float2(yl2[k]);
            s_y[2 * k]     = h.x + l.x;
            s_y[2 * k + 1] = h.y + l.y;
        }
    }

    // ---- row max from 16 tile maxima (warp 0) ----
    if (wid == 0) {
        float v = (lane < 16) ? g_tmax[(size_t)row * 16 + lane] : -3.4e38f;
        #pragma unroll
        for (int off = 16; off; off >>= 1)
            v = fmaxf(v, __shfl_xor_sync(0xffffffffu, v, off));
        if (lane == 0) red[0] = v;
    }
    __syncthreads();
    const float thr = red[0] - 22.5f;

    // ---- approx logits (8 per thread; w already folded in) ----
    float av[8];
    {
        const __half2* s2 = reinterpret_cast<const __half2*>(srow);
        const float2 a0 = __half22float2(s2[2 * t]);
        const float2 a1 = __half22float2(s2[2 * t + 1]);
        const float2 a2 = __half22float2(s2[512 + 2 * t]);
        const float2 a3 = __half22float2(s2[512 + 2 * t + 1]);
        av[0] = a0.x; av[1] = a0.y; av[2] = a1.x; av[3] = a1.y;
        av[4] = a2.x; av[5] = a2.y; av[6] = a3.x; av[7] = a3.y;
    }
    int cols[8];
    cols[0] = 4 * t;           cols[1] = 4 * t + 1;
    cols[2] = 4 * t + 2;       cols[3] = 4 * t + 3;
    cols[4] = 1024 + 4 * t;    cols[5] = 1024 + 4 * t + 1;
    cols[6] = 1024 + 4 * t + 2; cols[7] = 1024 + 4 * t + 3;

    // ---- deterministic candidate compaction ----
    int cnt = 0;
    #pragma unroll
    for (int j = 0; j < 8; ++j)
        if (av[j] > thr) cnt++;
    int inc = cnt;
    #pragma unroll
    for (int off = 1; off < 32; off <<= 1) {
        int n = __shfl_up_sync(0xffffffffu, inc, off);
        if (lane >= off) inc += n;
    }
    if (lane == 31) s_wtot[wid] = inc;
    __syncthreads();
    if (t == 0) {
        int run = 0;
        #pragma unroll
        for (int wI = 0; wI < 8; ++wI) {
            s_wbase[wI] = run;
            run += s_wtot[wI];
        }
        s_ncand = run;
    }
    __syncthreads();
    int ofs = s_wbase[wid] + (inc - cnt);
    #pragma unroll
    for (int j = 0; j < 8; ++j) {
        if (av[j] > thr) {
            s_idx[ofs] = cols[j];
            ofs++;
        }
    }
    __syncthreads();
    const int ncand = s_ncand;

    // ---- exact rescore: one warp per candidate ----
    for (int k = wid; k < ncand; k += 8) {
        const int j = s_idx[k];
        const __half2* xh2 = reinterpret_cast<const __half2*>(
            g_xh + (size_t)(wbase + j) * HID);
        const __half2* xl2 = reinterpret_cast<const __half2*>(
            g_xl + (size_t)(wbase + j) * HID);
        float part = 0.f;
        for (int d = lane; d < 512; d += 32) {
            const float2 h = __half22float2(xh2[d]);
            const float2 l = __half22float2(xl2[d]);
            part += s_y[2 * d] * (h.x + l.x) + s_y[2 * d + 1] * (h.y + l.y);
        }
        #pragma unroll
        for (int off = 16; off; off >>= 1)
            part += __shfl_xor_sync(0xffffffffu, part, off);
        if (lane == 0) s_logit[k] = part + g_w[wbase + j];
    }
    __syncthreads();

    // ---- exact max over candidates ----
    float m2 = -3.4e38f;
    for (int k = t; k < ncand; k += 256) m2 = fmaxf(m2, s_logit[k]);
    #pragma unroll
    for (int off = 16; off; off >>= 1)
        m2 = fmaxf(m2, __shfl_xor_sync(0xffffffffu, m2, off));
    if (lane == 0) red[wid] = m2;
    __syncthreads();
    if (t < 8) {
        float mm = red[t];
        #pragma unroll
        for (int off = 4; off; off >>= 1)
            mm = fmaxf(mm, __shfl_xor_sync(0xffu, mm, off));
        if (t == 0) red[0] = mm;
    }
    __syncthreads();
    m2 = red[0];
    __syncthreads();

    // ---- exact gate + exp + sum ----
    const float thr2 = m2 - 17.0f;
    float ssum = 0.f;
    for (int k = t; k < ncand; k += 256) {
        const float l = s_logit[k];
        const float e = (l > thr2) ? __expf(l - m2) : 0.f;
        s_logit[k] = e;
        ssum += e;
    }
    #pragma unroll
    for (int off = 16; off; off >>= 1)
        ssum += __shfl_xor_sync(0xffffffffu, ssum, off);
    if (lane == 0) red[wid] = ssum;
    __syncthreads();
    if (t < 8) {
        float ss = red[t];
        #pragma unroll
        for (int off = 4; off; off >>= 1)
            ss += __shfl_xor_sync(0xffu, ss, off);
        if (t == 0) red[0] = ss;
    }
    __syncthreads();
    const float inv = 1.0f / red[0];
    __syncthreads();

    // ---- gather: out[row,:] = sum_k p_k * v[idx_k,:] ----
    const __half* vbase = g_vh + (size_t)batch * SEQ * HID;
    float acc0 = 0.f, acc1 = 0.f, acc2 = 0.f, acc3 = 0.f;
    for (int k = 0; k < ncand; ++k) {
        const float pv = s_logit[k] * inv;
        if (pv != 0.f) {
            const __half2* vr = reinterpret_cast<const __half2*>(
                vbase + (size_t)s_idx[k] * HID) + 2 * t;
            const float2 f0 = __half22float2(vr[0]);
            const float2 f1 = __half22float2(vr[1]);
            acc0 += pv * f0.x; acc1 += pv * f0.y;
            acc2 += pv * f1.x; acc3 += pv * f1.y;
        }
    }
    float4 o;
    o.x = acc0; o.y = acc1; o.z = acc2; o.w = acc3;
    *reinterpret_cast<float4*>(out + (size_t)row * HID + 4 * t) = o;
}

// ----------------------------------------------------------------------------
// launch
// ----------------------------------------------------------------------------
#define GEMM_SMEM 98304

extern "C" void kernel_launch(void* const* d_in, const int* in_sizes, int n_in,
                              void* d_out, int out_size)
{
    (void)in_sizes; (void)n_in; (void)out_size;
    const float* x  = (const float*)d_in[0];
    const float* Wq = (const float*)d_in[1];
    const float* bq = (const float*)d_in[2];
    const float* Wk = (const float*)d_in[3];
    const float* Wv = (const float*)d_in[5];
    const float* bv = (const float*)d_in[6];
    float* out = (float*)d_out;

    cudaFuncSetAttribute(mv_kernel,
        cudaFuncAttributeMaxDynamicSharedMemorySize, GEMM_SMEM);
    cudaFuncSetAttribute(y_kernel,
        cudaFuncAttributeMaxDynamicSharedMemorySize, GEMM_SMEM);
    cudaFuncSetAttribute(scores_kernel,
        cudaFuncAttributeMaxDynamicSharedMemorySize, GEMM_SMEM);

    // 0) prep
    split_x_kernel<<<MTOT * HID / 4 / 256, 256>>>(x);
    wq_transpose_kernel<<<dim3(HID / 32, HID / 32), 256>>>(Wq);
    wkv_prep_kernel<<<dim3(HID * HID / 4 / 256, 1, 2), 256>>>(Wk, Wv);
    t2_part_kernel<<<dim3(HID / 256, 32), 256>>>(Wk, bq);
    t2_reduce_kernel<<<HID / 256, 256>>>();
    w_kernel<<<MTOT / 4, 128>>>(x);

    // 1) merged: M = Wq^T Wk (split3) + v = x Wv^T + bv (1x)
    mv_kernel<<<dim3(HID / 128, 8 + MTOT / 128), 256, GEMM_SMEM>>>(bv);
    // 2) y = x M (split3) -> yh/yl + yq
    y_kernel<<<dim3(HID / 128, MTOT / 128), 256, GEMM_SMEM>>>();
    // 3) approx scores+w (int8) -> fp16 logits + per-tile row maxima
    scores_kernel<<<dim3(SEQ / 128, SEQ / 128, BATCH), 256, GEMM_SMEM>>>();
    // 4) fused gate + exact rescore + softmax + sparse P.v gather -> out
    softmax_rescore_pv_kernel<<<BATCH * SEQ, 256>>>(out);
}